// round 2
// baseline (speedup 1.0000x reference)
#include <cuda_runtime.h>
#include <mma.h>
#include <cstdint>
#include <cstddef>

using namespace nvcuda;

// Problem constants
#define kT 512
#define kB 64
#define kH 1024
#define kG 3072
#define kL 4

// Recurrence kernel config: each CTA owns HS hidden units -> NR = 3*HS gate rows
#define HS 16
#define NR 48
#define NCTA 64          /* kH / HS */
#define RTH 256          /* 8 warps */
#define REC_SMEM ((NR * kH + 2 * kB * NR) * 4)   /* 221184 bytes */

// gi GEMM config
#define GBM 128
#define GBN 128
#define GTH 512
#define GI_SMEM (GBM * GBN * 4)   /* 64KB epilogue staging */

// ---------------------------------------------------------------------------
// Scratch (device globals: allocation inside kernel_launch is forbidden)
// ---------------------------------------------------------------------------
__device__ float g_seqA[kT * kB * kH];                 // 128 MB
__device__ float g_seqB[kT * kB * kH];                 // 128 MB
__device__ float g_gi[(size_t)kT * kB * kG];           // 384 MB
__device__ unsigned g_count;
__device__ unsigned g_release;

__global__ void reset_bar_kernel() { g_count = 0u; g_release = 0u; }

// Grid barrier across NCTA co-resident CTAs (monotonic count + release flag,
// counters reset by reset_bar_kernel before every recurrence launch).
__device__ __forceinline__ void grid_barrier(unsigned idx) {
  __syncthreads();
  if (threadIdx.x == 0) {
    __threadfence();
    unsigned old = atomicAdd(&g_count, 1u);
    if (old == (unsigned)NCTA * (idx + 1u) - 1u) {
      __threadfence();
      *(volatile unsigned*)&g_release = idx + 1u;
    } else {
      while (*(volatile unsigned*)&g_release < idx + 1u) { }
    }
    __threadfence();
  }
  __syncthreads();
}

__device__ __forceinline__ float sigmoidf_(float x) {
  return 1.0f / (1.0f + expf(-x));
}

// ---------------------------------------------------------------------------
// gi GEMM: C[M=T*B, N=3H] = A[M,K=H] @ W[N,K]^T + (b_ih + b_hh for r,z gates)
// tf32 wmma, CTA tile 128x128, 16 warps (4x4), warp tile 32x32.
// ---------------------------------------------------------------------------
__global__ void __launch_bounds__(GTH, 1) gi_kernel(
    const float* __restrict__ A,
    const float* __restrict__ W,
    const float* __restrict__ bi,
    const float* __restrict__ bh,
    float* __restrict__ C) {
  extern __shared__ float cs[];
  const int tid = threadIdx.x;
  const int wid = tid >> 5;
  const int wm = wid >> 2;
  const int wn = wid & 3;
  const int tm = blockIdx.y * GBM;
  const int tn = blockIdx.x * GBN;

  wmma::fragment<wmma::accumulator, 16, 16, 8, float> acc[2][2];
#pragma unroll
  for (int i = 0; i < 2; i++)
#pragma unroll
    for (int j = 0; j < 2; j++) wmma::fill_fragment(acc[i][j], 0.0f);

  const float* ab = A + (size_t)(tm + wm * 32) * kH;
  const float* wb = W + (size_t)(tn + wn * 32) * kH;

#pragma unroll 2
  for (int k = 0; k < kH; k += 8) {
    wmma::fragment<wmma::matrix_a, 16, 16, 8, wmma::precision::tf32, wmma::row_major> fa[2];
    wmma::fragment<wmma::matrix_b, 16, 16, 8, wmma::precision::tf32, wmma::col_major> fb[2];
#pragma unroll
    for (int i = 0; i < 2; i++) {
      wmma::load_matrix_sync(fa[i], ab + (size_t)i * 16 * kH + k, kH);
#pragma unroll
      for (int e = 0; e < 4; e++) fa[i].x[e] = wmma::__float_to_tf32(fa[i].x[e]);
    }
#pragma unroll
    for (int j = 0; j < 2; j++) {
      wmma::load_matrix_sync(fb[j], wb + (size_t)j * 16 * kH + k, kH);
#pragma unroll
      for (int e = 0; e < 4; e++) fb[j].x[e] = wmma::__float_to_tf32(fb[j].x[e]);
    }
#pragma unroll
    for (int i = 0; i < 2; i++)
#pragma unroll
      for (int j = 0; j < 2; j++) wmma::mma_sync(acc[i][j], fa[i], fb[j], acc[i][j]);
  }

#pragma unroll
  for (int i = 0; i < 2; i++)
#pragma unroll
    for (int j = 0; j < 2; j++)
      wmma::store_matrix_sync(cs + (wm * 32 + i * 16) * GBN + wn * 32 + j * 16,
                              acc[i][j], GBN, wmma::mem_row_major);
  __syncthreads();

  for (int e = tid; e < GBM * GBN; e += GTH) {
    int r = e >> 7;           // /GBN
    int c = e & (GBN - 1);
    int n = tn + c;
    // fold b_hh into r,z gate pre-activations (additive); n gate keeps b_hh
    // inside the r*(gh_n + b_hh_n) term handled in the recurrence epilogue.
    float bias = bi[n] + (n < 2 * kH ? bh[n] : 0.0f);
    C[(size_t)(tm + r) * kG + n] = cs[e] + bias;
  }
}

// ---------------------------------------------------------------------------
// Recurrence: persistent kernel, one layer. NCTA=64 CTAs, each owns 16 hidden
// units (48 gate rows of w_hh, tf32-converted, resident in SMEM all 512 steps).
// Per step: gh-slice GEMM (wmma tf32, A=h_{t-1} streamed from global),
// gate epilogue, write h_t to the layer output sequence, grid barrier.
// ---------------------------------------------------------------------------
__global__ void __launch_bounds__(RTH, 1) rec_kernel(
    const float* __restrict__ gi,     // [kT*kB, kG], biases pre-added
    const float* __restrict__ whh_l,  // [kG, kH]
    const float* __restrict__ h0_l,   // [kB, kH]
    float* __restrict__ seq_out,      // [kT, kB, kH]
    float* __restrict__ hfin,         // [kB, kH]
    const float* __restrict__ bhh_l)  // [kG]
{
  extern __shared__ float sm[];
  float* wsm = sm;                    // [NR][kH]
  float* ghs = sm + NR * kH;          // [2][kB][NR] (two K-half partials)
  const int tid = threadIdx.x;
  const int j0 = blockIdx.x * HS;

  // Stage weight slice: local rows 0-15 = r gate, 16-31 = z, 32-47 = n.
  for (int idx = tid; idx < NR * (kH / 4); idx += RTH) {
    int row = idx >> 8;               // kH/4 = 256 float4 per row
    int c4 = idx & 255;
    int gr = (row >> 4) * kH + j0 + (row & 15);
    float4 v = ((const float4*)(whh_l + (size_t)gr * kH))[c4];
    v.x = wmma::__float_to_tf32(v.x);
    v.y = wmma::__float_to_tf32(v.y);
    v.z = wmma::__float_to_tf32(v.z);
    v.w = wmma::__float_to_tf32(v.w);
    ((float4*)(wsm + (size_t)row * kH))[c4] = v;
  }
  __syncthreads();

  const int wid = tid >> 5;
  const int km = wid & 1;             // K half
  const int wm = wid >> 1;            // M (batch) quarter
  const int kbeg = km * (kH / 2);

  for (int t = 0; t < kT; t++) {
    const float* hprev = (t == 0) ? h0_l : (seq_out + (size_t)(t - 1) * kB * kH);

    wmma::fragment<wmma::accumulator, 16, 16, 8, float> acc[3];
#pragma unroll
    for (int g = 0; g < 3; g++) wmma::fill_fragment(acc[g], 0.0f);

    const float* abase = hprev + (size_t)(wm * 16) * kH;
#pragma unroll 2
    for (int kk = 0; kk < kH / 2; kk += 8) {
      int k = kbeg + kk;
      wmma::fragment<wmma::matrix_a, 16, 16, 8, wmma::precision::tf32, wmma::row_major> fa;
      wmma::load_matrix_sync(fa, abase + k, kH);
#pragma unroll
      for (int e = 0; e < 4; e++) fa.x[e] = wmma::__float_to_tf32(fa.x[e]);
#pragma unroll
      for (int g = 0; g < 3; g++) {
        wmma::fragment<wmma::matrix_b, 16, 16, 8, wmma::precision::tf32, wmma::col_major> fb;
        wmma::load_matrix_sync(fb, wsm + (size_t)(g * 16) * kH + k, kH);
        wmma::mma_sync(acc[g], fa, fb, acc[g]);
      }
    }
#pragma unroll
    for (int g = 0; g < 3; g++)
      wmma::store_matrix_sync(ghs + km * kB * NR + (wm * 16) * NR + g * 16,
                              acc[g], NR, wmma::mem_row_major);
    __syncthreads();

    // Gate epilogue: 64 batches x 16 hidden units owned by this CTA.
    for (int e = tid; e < kB * HS; e += RTH) {
      int b = e >> 4;
      int jj = e & (HS - 1);
      const float* g0 = ghs + b * NR;
      const float* g1 = ghs + kB * NR + b * NR;
      float ghr = g0[jj] + g1[jj];
      float ghz = g0[HS + jj] + g1[HS + jj];
      float ghn = g0[2 * HS + jj] + g1[2 * HS + jj];
      int jg = j0 + jj;
      size_t gib = ((size_t)t * kB + b) * kG;
      float gir = gi[gib + jg];
      float giz = gi[gib + kH + jg];
      float gin = gi[gib + 2 * kH + jg];
      float hp = hprev[(size_t)b * kH + jg];
      float r = sigmoidf_(gir + ghr);
      float z = sigmoidf_(giz + ghz);
      float n = tanhf(gin + r * (ghn + bhh_l[2 * kH + jg]));
      float h = (1.0f - z) * n + z * hp;
      seq_out[(size_t)t * kB * kH + (size_t)b * kH + jg] = h;
      if (t == kT - 1) hfin[(size_t)b * kH + jg] = h;
    }
    grid_barrier((unsigned)t);
  }
}

// ---------------------------------------------------------------------------
// Launch: for each layer, batched input GEMM then persistent recurrence.
// Layer l output sequence ping-pongs between g_seqA / g_seqB.
// ---------------------------------------------------------------------------
extern "C" void kernel_launch(void* const* d_in, const int* in_sizes, int n_in,
                              void* d_out, int out_size) {
  (void)in_sizes; (void)n_in; (void)out_size;
  const float* x   = (const float*)d_in[0];  // [T,B,IN]
  const float* h0  = (const float*)d_in[1];  // [L,B,H]
  const float* wih = (const float*)d_in[2];  // [L,3H,IN]
  const float* whh = (const float*)d_in[3];  // [L,3H,H]
  const float* bih = (const float*)d_in[4];  // [L,3H]
  const float* bhh = (const float*)d_in[5];  // [L,3H]
  float* out = (float*)d_out;                // [L,B,H]

  float *seqA = nullptr, *seqB = nullptr, *gi = nullptr;
  cudaGetSymbolAddress((void**)&seqA, g_seqA);
  cudaGetSymbolAddress((void**)&seqB, g_seqB);
  cudaGetSymbolAddress((void**)&gi, g_gi);

  cudaFuncSetAttribute(gi_kernel, cudaFuncAttributeMaxDynamicSharedMemorySize, GI_SMEM);
  cudaFuncSetAttribute(rec_kernel, cudaFuncAttributeMaxDynamicSharedMemorySize, REC_SMEM);

  dim3 ggrid(kG / GBN, (kT * kB) / GBM);
  for (int l = 0; l < kL; l++) {
    const float* in_seq = (l == 0) ? x : ((l & 1) ? seqA : seqB);
    float* out_seq = (l & 1) ? seqB : seqA;
    gi_kernel<<<ggrid, GTH, GI_SMEM>>>(in_seq,
                                       wih + (size_t)l * kG * kH,
                                       bih + (size_t)l * kG,
                                       bhh + (size_t)l * kG,
                                       gi);
    reset_bar_kernel<<<1, 1>>>();
    rec_kernel<<<NCTA, RTH, REC_SMEM>>>(gi,
                                        whh + (size_t)l * kG * kH,
                                        h0 + (size_t)l * kB * kH,
                                        out_seq,
                                        out + (size_t)l * kB * kH,
                                        bhh + (size_t)l * kG);
  }
}

// round 3
// speedup vs baseline: 2.1927x; 2.1927x over previous
#include <cuda_runtime.h>
#include <mma.h>
#include <cstdint>
#include <cstddef>

using namespace nvcuda;

// Problem constants
#define kT 512
#define kB 64
#define kH 1024
#define kG 3072
#define kL 4

// Recurrence config: 64 CTAs, each owns HS=16 hidden units (NR=48 gate rows).
#define HS 16
#define NR 48
#define NCTA 64
#define RTH 256                     /* 8 warps: 4 K-quarters x 2 N-halves */
#define KITERS 128                  /* kH / 8 */
#define GHS_LD 66                   /* padded row stride of partial buffers */
#define SA_FLOATS (3 * KITERS * 32 * 4)          /* 49152 fragment-packed W */
#define REC_SMEM ((SA_FLOATS + 2 * NR * GHS_LD) * 4)  /* 221952 B */

// gi GEMM config (unchanged from R1)
#define GBM 128
#define GBN 128
#define GTH 512
#define GI_SMEM (GBM * GBN * 4)

// ---------------------------------------------------------------------------
// Scratch (device globals: no allocation allowed)
// ---------------------------------------------------------------------------
__device__ float g_seqA[kT * kB * kH];
__device__ float g_seqB[kT * kB * kH];
__device__ float g_gi[(size_t)kT * kB * kG];
__device__ float g_hT[2 * kB * kH];   // packed-transposed h ping-pong, tf32 values
__device__ unsigned g_count;
__device__ unsigned g_release;

__global__ void reset_bar_kernel() { g_count = 0u; g_release = 0u; }

__device__ __forceinline__ void grid_barrier(unsigned idx) {
  __syncthreads();
  if (threadIdx.x == 0) {
    __threadfence();
    unsigned old = atomicAdd(&g_count, 1u);
    if (old == (unsigned)NCTA * (idx + 1u) - 1u) {
      __threadfence();
      *(volatile unsigned*)&g_release = idx + 1u;
    } else {
      while (*(volatile unsigned*)&g_release < idx + 1u) { }
    }
    __threadfence();
  }
  __syncthreads();
}

__device__ __forceinline__ float sigmoidf_(float x) {
  return 1.0f / (1.0f + expf(-x));
}

// packed-transposed h index: pairs (j, j+4) adjacent so B-fragment = LDG.64
__device__ __forceinline__ int hT_index(int j, int b) {
  return (((j >> 3) * 64 + b) << 3) + ((j & 3) << 1) + ((j >> 2) & 1);
}

// mma.sync m16n8k8 tf32: D += A*B. A regs: (r,c),(r+8,c),(r,c+4),(r+8,c+4)
// with r=lane>>2, c=lane&3. B regs: (k=lane&3,n=lane>>2),(k+4,n).
// C regs: (r,2c),(r,2c+1),(r+8,2c),(r+8,2c+1).
#define MMA_TF32(d, a, b0, b1)                                              \
  asm volatile(                                                             \
      "mma.sync.aligned.m16n8k8.row.col.f32.tf32.tf32.f32 "                 \
      "{%0,%1,%2,%3}, {%4,%5,%6,%7}, {%8,%9}, {%0,%1,%2,%3};"               \
      : "+f"(d[0]), "+f"(d[1]), "+f"(d[2]), "+f"(d[3])                      \
      : "r"(a.x), "r"(a.y), "r"(a.z), "r"(a.w), "r"(b0), "r"(b1))

// ---------------------------------------------------------------------------
// pack h0 of one layer into g_hT buffer 0 (tf32-converted)
// ---------------------------------------------------------------------------
__global__ void pack_h0_kernel(const float* __restrict__ h0_l) {
  int idx = blockIdx.x * blockDim.x + threadIdx.x;   // 0 .. kB*kH-1
  int b = idx >> 10;
  int j = idx & (kH - 1);
  g_hT[hT_index(j, b)] = wmma::__float_to_tf32(h0_l[idx]);
}

// ---------------------------------------------------------------------------
// gi GEMM (unchanged): C[T*B, 3H] = A @ W^T + biases
// ---------------------------------------------------------------------------
__global__ void __launch_bounds__(GTH, 1) gi_kernel(
    const float* __restrict__ A,
    const float* __restrict__ W,
    const float* __restrict__ bi,
    const float* __restrict__ bh,
    float* __restrict__ C) {
  extern __shared__ float cs[];
  const int tid = threadIdx.x;
  const int wid = tid >> 5;
  const int wm = wid >> 2;
  const int wn = wid & 3;
  const int tm = blockIdx.y * GBM;
  const int tn = blockIdx.x * GBN;

  wmma::fragment<wmma::accumulator, 16, 16, 8, float> acc[2][2];
#pragma unroll
  for (int i = 0; i < 2; i++)
#pragma unroll
    for (int j = 0; j < 2; j++) wmma::fill_fragment(acc[i][j], 0.0f);

  const float* ab = A + (size_t)(tm + wm * 32) * kH;
  const float* wb = W + (size_t)(tn + wn * 32) * kH;

#pragma unroll 2
  for (int k = 0; k < kH; k += 8) {
    wmma::fragment<wmma::matrix_a, 16, 16, 8, wmma::precision::tf32, wmma::row_major> fa[2];
    wmma::fragment<wmma::matrix_b, 16, 16, 8, wmma::precision::tf32, wmma::col_major> fb[2];
#pragma unroll
    for (int i = 0; i < 2; i++) {
      wmma::load_matrix_sync(fa[i], ab + (size_t)i * 16 * kH + k, kH);
#pragma unroll
      for (int e = 0; e < 4; e++) fa[i].x[e] = wmma::__float_to_tf32(fa[i].x[e]);
    }
#pragma unroll
    for (int j = 0; j < 2; j++) {
      wmma::load_matrix_sync(fb[j], wb + (size_t)j * 16 * kH + k, kH);
#pragma unroll
      for (int e = 0; e < 4; e++) fb[j].x[e] = wmma::__float_to_tf32(fb[j].x[e]);
    }
#pragma unroll
    for (int i = 0; i < 2; i++)
#pragma unroll
      for (int j = 0; j < 2; j++) wmma::mma_sync(acc[i][j], fa[i], fb[j], acc[i][j]);
  }

#pragma unroll
  for (int i = 0; i < 2; i++)
#pragma unroll
    for (int j = 0; j < 2; j++)
      wmma::store_matrix_sync(cs + (wm * 32 + i * 16) * GBN + wn * 32 + j * 16,
                              acc[i][j], GBN, wmma::mem_row_major);
  __syncthreads();

  for (int e = tid; e < GBM * GBN; e += GTH) {
    int r = e >> 7;
    int c = e & (GBN - 1);
    int n = tn + c;
    float bias = bi[n] + (n < 2 * kH ? bh[n] : 0.0f);
    C[(size_t)(tm + r) * kG + n] = cs[e] + bias;
  }
}

// ---------------------------------------------------------------------------
// Recurrence: gh^T[48, 64] = W_slice[48, 1024] @ hT[1024, 64] per CTA per step.
// Weights fragment-packed in SMEM (conflict-free LDS.128); h as B operand from
// packed global layout (coalesced LDG.64, read exactly once).
// 8 warps = 4 K-quarters (K=256) x 2 N-halves (32 batches).
// ---------------------------------------------------------------------------
__global__ void __launch_bounds__(RTH, 1) rec_kernel(
    const float* __restrict__ gi,
    const float* __restrict__ whh_l,
    const float* __restrict__ h0_l,
    float* __restrict__ seq_out,
    float* __restrict__ hfin,
    const float* __restrict__ bhh_l) {
  extern __shared__ float sm[];
  float* sA = sm;                                 // [3][KITERS][32 lanes][4]
  float* buf0 = sm + SA_FLOATS;                   // [NR][GHS_LD] K-partial 0+2
  float* buf1 = buf0 + NR * GHS_LD;               // [NR][GHS_LD] K-partial 1+3
  const int tid = threadIdx.x;
  const int lane = tid & 31;
  const int wid = tid >> 5;
  const int j0 = blockIdx.x * HS;

  // Stage W_hh slice in exact A-fragment order (tf32), one LDS.128 per frag.
  for (int idx = tid; idx < SA_FLOATS; idx += RTH) {
    int e = idx & 3;
    int ln = (idx >> 2) & 31;
    int ki = (idx >> 7) & (KITERS - 1);
    int mt = idx >> 14;                            // gate 0..2
    int rr = (ln >> 2) + ((e & 1) << 3);           // local row in 16-tile
    int k = ki * 8 + (ln & 3) + ((e >> 1) << 2);
    float w = whh_l[(size_t)(mt * kH + j0 + rr) * kH + k];
    sA[idx] = wmma::__float_to_tf32(w);
  }
  __syncthreads();

  const int kg = wid & 3;           // K quarter
  const int nh = wid >> 2;          // N half (batches 32*nh ..)
  const int g4 = lane >> 2;
  const int l4 = lane & 3;
  const uint4* sAv = (const uint4*)sA;

  for (int t = 0; t < kT; t++) {
    const float2* hT = (const float2*)(g_hT + (size_t)(t & 1) * kB * kH);

    float acc[3][4][4];
#pragma unroll
    for (int mt = 0; mt < 3; mt++)
#pragma unroll
      for (int nt = 0; nt < 4; nt++)
#pragma unroll
        for (int e = 0; e < 4; e++) acc[mt][nt][e] = 0.0f;

#pragma unroll 2
    for (int i = 0; i < 32; i++) {
      int ki = kg * 32 + i;
      uint4 a0 = sAv[(0 * KITERS + ki) * 32 + lane];
      uint4 a1 = sAv[(1 * KITERS + ki) * 32 + lane];
      uint4 a2 = sAv[(2 * KITERS + ki) * 32 + lane];
      uint32_t bx[4], by[4];
#pragma unroll
      for (int nt = 0; nt < 4; nt++) {
        int n = (nh * 4 + nt) * 8 + g4;
        float2 p = hT[(ki * 64 + n) * 4 + l4];
        bx[nt] = __float_as_uint(p.x);
        by[nt] = __float_as_uint(p.y);
      }
#pragma unroll
      for (int nt = 0; nt < 4; nt++) {
        MMA_TF32(acc[0][nt], a0, bx[nt], by[nt]);
        MMA_TF32(acc[1][nt], a1, bx[nt], by[nt]);
        MMA_TF32(acc[2][nt], a2, bx[nt], by[nt]);
      }
    }

    // K-partial reduction: kg 0,1 write; kg 2,3 add.
    float* buf = (kg & 1) ? buf1 : buf0;
    if (kg < 2) {
#pragma unroll
      for (int mt = 0; mt < 3; mt++)
#pragma unroll
        for (int nt = 0; nt < 4; nt++) {
          int row = mt * 16 + g4;
          int col = (nh * 4 + nt) * 8 + (l4 << 1);
          *(float2*)(buf + row * GHS_LD + col) =
              make_float2(acc[mt][nt][0], acc[mt][nt][1]);
          *(float2*)(buf + (row + 8) * GHS_LD + col) =
              make_float2(acc[mt][nt][2], acc[mt][nt][3]);
        }
    }
    __syncthreads();
    if (kg >= 2) {
#pragma unroll
      for (int mt = 0; mt < 3; mt++)
#pragma unroll
        for (int nt = 0; nt < 4; nt++) {
          int row = mt * 16 + g4;
          int col = (nh * 4 + nt) * 8 + (l4 << 1);
          float2* p0 = (float2*)(buf + row * GHS_LD + col);
          float2* p1 = (float2*)(buf + (row + 8) * GHS_LD + col);
          float2 v0 = *p0, v1 = *p1;
          v0.x += acc[mt][nt][0]; v0.y += acc[mt][nt][1];
          v1.x += acc[mt][nt][2]; v1.y += acc[mt][nt][3];
          *p0 = v0; *p1 = v1;
        }
    }
    __syncthreads();

    // Gate epilogue
    const float* hprev = (t == 0) ? h0_l : (seq_out + (size_t)(t - 1) * kB * kH);
    float* hTn = g_hT + (size_t)((t + 1) & 1) * kB * kH;
    for (int e2 = tid; e2 < kB * HS; e2 += RTH) {
      int b = e2 >> 4;
      int jj = e2 & (HS - 1);
      float ghr = buf0[(0 * 16 + jj) * GHS_LD + b] + buf1[(0 * 16 + jj) * GHS_LD + b];
      float ghz = buf0[(1 * 16 + jj) * GHS_LD + b] + buf1[(1 * 16 + jj) * GHS_LD + b];
      float ghn = buf0[(2 * 16 + jj) * GHS_LD + b] + buf1[(2 * 16 + jj) * GHS_LD + b];
      int jg = j0 + jj;
      size_t gib = ((size_t)t * kB + b) * kG;
      float gir = gi[gib + jg];
      float giz = gi[gib + kH + jg];
      float gin = gi[gib + 2 * kH + jg];
      float hp = hprev[(size_t)b * kH + jg];
      float r = sigmoidf_(gir + ghr);
      float z = sigmoidf_(giz + ghz);
      float n = tanhf(gin + r * (ghn + bhh_l[2 * kH + jg]));
      float h = (1.0f - z) * n + z * hp;
      seq_out[(size_t)t * kB * kH + (size_t)b * kH + jg] = h;
      hTn[hT_index(jg, b)] = wmma::__float_to_tf32(h);
      if (t == kT - 1) hfin[(size_t)b * kH + jg] = h;
    }
    grid_barrier((unsigned)t);
  }
}

// ---------------------------------------------------------------------------
// Launch
// ---------------------------------------------------------------------------
extern "C" void kernel_launch(void* const* d_in, const int* in_sizes, int n_in,
                              void* d_out, int out_size) {
  (void)in_sizes; (void)n_in; (void)out_size;
  const float* x   = (const float*)d_in[0];
  const float* h0  = (const float*)d_in[1];
  const float* wih = (const float*)d_in[2];
  const float* whh = (const float*)d_in[3];
  const float* bih = (const float*)d_in[4];
  const float* bhh = (const float*)d_in[5];
  float* out = (float*)d_out;

  float *seqA = nullptr, *seqB = nullptr, *gi = nullptr;
  cudaGetSymbolAddress((void**)&seqA, g_seqA);
  cudaGetSymbolAddress((void**)&seqB, g_seqB);
  cudaGetSymbolAddress((void**)&gi, g_gi);

  cudaFuncSetAttribute(gi_kernel, cudaFuncAttributeMaxDynamicSharedMemorySize, GI_SMEM);
  cudaFuncSetAttribute(rec_kernel, cudaFuncAttributeMaxDynamicSharedMemorySize, REC_SMEM);

  dim3 ggrid(kG / GBN, (kT * kB) / GBM);
  for (int l = 0; l < kL; l++) {
    const float* in_seq = (l == 0) ? x : ((l & 1) ? seqA : seqB);
    float* out_seq = (l & 1) ? seqB : seqA;
    gi_kernel<<<ggrid, GTH, GI_SMEM>>>(in_seq,
                                       wih + (size_t)l * kG * kH,
                                       bih + (size_t)l * kG,
                                       bhh + (size_t)l * kG,
                                       gi);
    reset_bar_kernel<<<1, 1>>>();
    pack_h0_kernel<<<(kB * kH) / 256, 256>>>(h0 + (size_t)l * kB * kH);
    rec_kernel<<<NCTA, RTH, REC_SMEM>>>(gi,
                                        whh + (size_t)l * kG * kH,
                                        h0 + (size_t)l * kB * kH,
                                        out_seq,
                                        out + (size_t)l * kB * kH,
                                        bhh + (size_t)l * kG);
  }
}